// round 14
// baseline (speedup 1.0000x reference)
#include <cuda_runtime.h>
#include <cstdint>

// DotProductCostVolume via mma.sync tf32 band-GEMM + intra-CTA h-pipeline.
// out[b,d,h,w] = (1/32) * sum_c L[b,c,h,w]*R[b,c,h,w-d], 0 if w<d.
// B=4, C=32, H=256, W=512, D=64, fp32.
//
// CTA = (b, w-tile, 2 consecutive h rows), 256 threads / 8 warps.
// BOTH h-tiles are prefetched up front into separate 43KB smem buffers
// (dynamic smem 86KB/CTA, 2 CTAs/SM): tile1's DRAM transfer streams in while
// tile0 computes -> staging latency/bandwidth hidden inside the CTA instead of
// relying on cross-CTA phase luck (R13 profile: DRAM 46%, issue 34%).
// Per tile (same as R13, proven):
//   Ls[c][m]=L[c,w0+m] pitch 136; Rs[c][n]=R[c,w0-64+n] pitch 200 (zfill halo)
//   warp wd: band strip D[16wd..+16) x [16wd..+80), 40 m16n8k8.tf32 mmas,
//   scalar-LDS fragments (pitch mod 32 = 8 -> conflict-free), cvt.rna tf32.
//   out[d, w0+m] = D[m][m+64-d]/32 via T[64][132] transpose (overlays the
//   consumed buffer) then coalesced __stcs.

#define Bn 4
#define Cn 32
#define Hn 256
#define Wn 512
#define Dn 64
#define TW 128
#define NB 192
#define NT 256
#define NTILE 2
#define HW (Hn*Wn)
#define PL 136          // Ls pitch (floats)
#define PR 200          // Rs pitch (floats)
#define RS_OFF (Cn*PL)  // Rs offset inside a buffer (floats)
#define BUF (Cn*PL + Cn*PR)   // 10752 floats = 43008 B per tile buffer
#define TPITCH 132

__device__ __forceinline__ void cp16(uint32_t s, const void* g, bool v) {
    asm volatile("cp.async.ca.shared.global [%0], [%1], 16, %2;"
                 :: "r"(s), "l"(g), "r"(v ? 16u : 0u));
}
__device__ __forceinline__ uint32_t f2tf(float f) {
    uint32_t r;
    asm("cvt.rna.tf32.f32 %0, %1;" : "=r"(r) : "f"(f));
    return r;
}

__global__ __launch_bounds__(NT, 2)
void cost_volume_kernel(const float* __restrict__ left,
                        const float* __restrict__ right,
                        float* __restrict__ out)
{
    extern __shared__ __align__(16) float smem[];   // 2 * BUF floats (86KB)

    const int tile = blockIdx.x;        // 0..3
    const int h0   = blockIdx.y * NTILE;// 0,2,..,254
    const int b    = blockIdx.z;        // 0..3
    const int w0   = tile * TW;
    const int tid  = threadIdx.x;
    const int lane = tid & 31;
    const int wd   = tid >> 5;          // warp 0..7

    const uint32_t sbase = (uint32_t)__cvta_generic_to_shared(smem);

    // ---- Prefetch one (h, buffer) tile: 10 cp16/thread ----
    auto prefetch = [&](int h, int bi) {
        const float* lbase = left  + (long)(b * Cn) * HW + (long)h * Wn;
        const float* rbase = right + (long)(b * Cn) * HW + (long)h * Wn;
        const uint32_t bb = sbase + 4u * (uint32_t)(bi * BUF);
        #pragma unroll
        for (int it = 0; it < 4; it++) {            // Ls: 1024 cp16
            int idx = it * NT + tid;
            int c = idx >> 5, q = idx & 31;
            cp16(bb + 4u * (uint32_t)(c * PL + 4 * q),
                 lbase + (long)c * HW + w0 + 4 * q, true);
        }
        #pragma unroll
        for (int it = 0; it < 6; it++) {            // Rs: 1536 cp16, zfill halo
            int idx = it * NT + tid;
            int c = idx / 48, q = idx - c * 48;
            int gw = w0 - 64 + 4 * q;               // chunk entirely <0 or >=0
            bool v = (gw >= 0);
            cp16(bb + 4u * (uint32_t)(RS_OFF + c * PR + 4 * q),
                 rbase + (long)c * HW + (v ? gw : 0), v);
        }
        asm volatile("cp.async.commit_group;");
    };

    prefetch(h0 + 0, 0);
    prefetch(h0 + 1, 1);

    const int g  = lane >> 2;           // fragment group row 0..7
    const int tg = lane & 3;            // thread-in-group 0..3
    const int m0 = 16 * wd;

    #pragma unroll
    for (int t = 0; t < NTILE; t++) {
        if (t == 0) asm volatile("cp.async.wait_group 1;");
        else        asm volatile("cp.async.wait_group 0;");
        __syncthreads();

        float* bp = smem + t * BUF;

        // ---- Band MMA: warp wd -> D strip [m0, m0+16) x [m0, m0+80) ----
        float dacc[10][4];
        #pragma unroll
        for (int u = 0; u < 10; u++)
            #pragma unroll
            for (int r = 0; r < 4; r++)
                dacc[u][r] = 0.0f;

        #pragma unroll
        for (int ks = 0; ks < 4; ks++) {
            const int c8 = ks * 8;
            const float* Ar0 = bp + (c8 + tg) * PL + m0 + g;
            const float* Ar1 = bp + (c8 + tg + 4) * PL + m0 + g;
            uint32_t a0 = f2tf(Ar0[0]), a1 = f2tf(Ar0[8]);
            uint32_t a2 = f2tf(Ar1[0]), a3 = f2tf(Ar1[8]);
            #pragma unroll
            for (int u = 0; u < 10; u++) {
                const int n0 = m0 + 8 * u;
                uint32_t b0 = f2tf(bp[RS_OFF + (c8 + tg) * PR + n0 + g]);
                uint32_t b1 = f2tf(bp[RS_OFF + (c8 + tg + 4) * PR + n0 + g]);
                asm("mma.sync.aligned.m16n8k8.row.col.f32.tf32.tf32.f32 "
                    "{%0,%1,%2,%3}, {%4,%5,%6,%7}, {%8,%9}, {%0,%1,%2,%3};"
                    : "+f"(dacc[u][0]), "+f"(dacc[u][1]),
                      "+f"(dacc[u][2]), "+f"(dacc[u][3])
                    : "r"(a0), "r"(a1), "r"(a2), "r"(a3), "r"(b0), "r"(b1));
            }
        }
        __syncthreads();   // all fragment reads done; bp becomes T[64][132]

        // ---- Fragment -> T[d][m] diagonal scatter ----
        #pragma unroll
        for (int u = 0; u < 10; u++) {
            int nbase = m0 + 8 * u + 2 * tg;
            #pragma unroll
            for (int r = 0; r < 4; r++) {
                int m = m0 + g + 8 * (r >> 1);
                int n = nbase + (r & 1);
                int d = m + 64 - n;
                if (d >= 0 && d < Dn)
                    bp[d * TPITCH + m] = dacc[u][r] * 0.03125f;
            }
        }
        __syncthreads();

        // ---- T -> global, coalesced streaming stores ----
        {
            const int dd = tid >> 2;    // d 0..63
            const int wq = tid & 3;
            const float* rowp = bp + dd * TPITCH + 4 * wq;
            float* op = out + ((long)(b * Dn + dd) * Hn + (h0 + t)) * Wn
                            + w0 + 4 * wq;
            #pragma unroll
            for (int k = 0; k < 8; k++) {
                float4 v = *(const float4*)(rowp + 16 * k);
                __stcs((float4*)(op + 16 * k), v);
            }
        }
        if (t + 1 < NTILE) __syncthreads();
    }
}

extern "C" void kernel_launch(void* const* d_in, const int* in_sizes, int n_in,
                              void* d_out, int out_size)
{
    const float* left  = (const float*)d_in[0];
    const float* right = (const float*)d_in[1];
    float* out = (float*)d_out;

    static_assert(2 * BUF * sizeof(float) == 86016, "smem size");
    cudaFuncSetAttribute(cost_volume_kernel,
                         cudaFuncAttributeMaxDynamicSharedMemorySize,
                         2 * BUF * sizeof(float));

    dim3 grid(Wn / TW, Hn / NTILE, Bn);   // (4, 128, 4) = 2048 CTAs
    cost_volume_kernel<<<grid, NT, 2 * BUF * sizeof(float)>>>(left, right, out);
}

// round 15
// speedup vs baseline: 1.0586x; 1.0586x over previous
#include <cuda_runtime.h>
#include <cstdint>

// DotProductCostVolume via mma.sync tf32 band-GEMM with split-K staged pipeline.
// out[b,d,h,w] = (1/32) * sum_c L[b,c,h,w]*R[b,c,h,w-d], 0 if w<d.
// B=4, C=32, H=256, W=512, D=64, fp32.
//
// R13 base (62us) + one change: staging is split into 4 channel-groups
// (8 channels each, ~17.5KB, own cp.async commit group). MMA k-step ks only
// needs channels 8ks..8ks+7, so compute starts after group 0 lands
// (wait_group 3) while groups 1-3 stream in under the tensor-core work.
// Exposed staging wait drops from 70KB to ~17.5KB per CTA.
//
// Per CTA (b, h, 128-wide w tile), 256 threads / 8 warps:
//   Ls[c][m]=L[c,w0+m] pitch 136; Rs[c][n]=R[c,w0-64+n] pitch 200 (zfill halo
//   -> w<d masking automatic). Scalar-LDS fragments (pitch mod 32 = 8 ->
//   conflict-free), cvt.rna tf32; warp wd computes band strip
//   D[16wd..+16) x [16wd..+80) with 40 m16n8k8 mmas.
//   out[d, w0+m] = D[m][m+64-d]/32 via T[64][132] transpose -> __stcs.

#define Bn 4
#define Cn 32
#define Hn 256
#define Wn 512
#define Dn 64
#define TW 128
#define NB 192
#define NT 256
#define HW (Hn*Wn)
#define PL 136          // Ls pitch (floats)
#define PR 200          // Rs pitch (floats)
#define RS_OFF (Cn*PL)  // Rs starts at float 4352
#define TPITCH 132

__device__ __forceinline__ void cp16(uint32_t s, const void* g, bool v) {
    asm volatile("cp.async.ca.shared.global [%0], [%1], 16, %2;"
                 :: "r"(s), "l"(g), "r"(v ? 16u : 0u));
}
__device__ __forceinline__ uint32_t f2tf(float f) {
    uint32_t r;
    asm("cvt.rna.tf32.f32 %0, %1;" : "=r"(r) : "f"(f));
    return r;
}
template <int N>
__device__ __forceinline__ void cp_wait() {
    asm volatile("cp.async.wait_group %0;" :: "n"(N));
}

__global__ __launch_bounds__(NT, 2)
void cost_volume_kernel(const float* __restrict__ left,
                        const float* __restrict__ right,
                        float* __restrict__ out)
{
    // Ls 4352 + Rs 6400 = 10752 floats (42KB); reused as T[64][132] (33.8KB).
    __shared__ __align__(16) float smem[Cn * PL + Cn * PR];

    const int tile = blockIdx.x;    // 0..3
    const int h    = blockIdx.y;    // 0..255
    const int b    = blockIdx.z;    // 0..3
    const int w0   = tile * TW;
    const int tid  = threadIdx.x;
    const int lane = tid & 31;
    const int wd   = tid >> 5;      // warp 0..7

    const float* lbase = left  + (long)(b * Cn) * HW + (long)h * Wn;
    const float* rbase = right + (long)(b * Cn) * HW + (long)h * Wn;
    const uint32_t sbase = (uint32_t)__cvta_generic_to_shared(smem);

    // ---- Stage in 4 channel-groups (8 channels each), one commit per group ----
    #pragma unroll
    for (int gidx = 0; gidx < 4; gidx++) {
        const int c0 = gidx * 8;
        // L: 8 rows x 32 chunks = 256 cp16 (1/thread)
        {
            int c = c0 + (tid >> 5), q = tid & 31;
            cp16(sbase + 4u * (uint32_t)(c * PL + 4 * q),
                 lbase + (long)c * HW + w0 + 4 * q, true);
        }
        // R: 8 rows x 48 chunks = 384 cp16 (1.5/thread), zfill halo
        #pragma unroll
        for (int it = 0; it < 2; it++) {
            int idx = it * NT + tid;
            if (idx < 384) {
                int c = c0 + idx / 48, q = idx % 48;
                int gw = w0 - 64 + 4 * q;       // chunk entirely <0 or >=0
                bool v = (gw >= 0);
                cp16(sbase + 4u * (uint32_t)(RS_OFF + c * PR + 4 * q),
                     rbase + (long)c * HW + (v ? gw : 0), v);
            }
        }
        asm volatile("cp.async.commit_group;");
    }

    // ---- Band MMA: warp wd -> D strip [16wd,16wd+16) x [16wd,16wd+80) ----
    const int g  = lane >> 2;           // fragment group row 0..7
    const int tg = lane & 3;            // thread-in-group 0..3
    const int m0 = 16 * wd;

    float dacc[10][4];
    #pragma unroll
    for (int u = 0; u < 10; u++)
        #pragma unroll
        for (int r = 0; r < 4; r++)
            dacc[u][r] = 0.0f;

    #pragma unroll
    for (int ks = 0; ks < 4; ks++) {
        // Group ks has landed once <= (3-ks) groups remain pending.
        if      (ks == 0) cp_wait<3>();
        else if (ks == 1) cp_wait<2>();
        else if (ks == 2) cp_wait<1>();
        else              cp_wait<0>();
        __syncthreads();

        const int c8 = ks * 8;
        // A fragment (row-major m16k8): a0=(g,tg) a1=(g+8,tg) a2=(g,tg+4) a3=(g+8,tg+4)
        const float* Ar0 = smem + (c8 + tg) * PL + m0 + g;
        const float* Ar1 = smem + (c8 + tg + 4) * PL + m0 + g;
        uint32_t a0 = f2tf(Ar0[0]), a1 = f2tf(Ar0[8]);
        uint32_t a2 = f2tf(Ar1[0]), a3 = f2tf(Ar1[8]);
        #pragma unroll
        for (int u = 0; u < 10; u++) {
            const int n0 = m0 + 8 * u;
            // B fragment (col-major k8n8): b0=(k=tg, n=g) b1=(k=tg+4, n=g)
            uint32_t b0 = f2tf(smem[RS_OFF + (c8 + tg) * PR + n0 + g]);
            uint32_t b1 = f2tf(smem[RS_OFF + (c8 + tg + 4) * PR + n0 + g]);
            asm("mma.sync.aligned.m16n8k8.row.col.f32.tf32.tf32.f32 "
                "{%0,%1,%2,%3}, {%4,%5,%6,%7}, {%8,%9}, {%0,%1,%2,%3};"
                : "+f"(dacc[u][0]), "+f"(dacc[u][1]),
                  "+f"(dacc[u][2]), "+f"(dacc[u][3])
                : "r"(a0), "r"(a1), "r"(a2), "r"(a3), "r"(b0), "r"(b1));
        }
    }
    __syncthreads();   // all smem reads done; smem becomes T[64][132]

    // ---- Fragment -> T[d][m] diagonal scatter ----
    // dacc[u]: d0=(m0+g, n0+2tg) d1=(.., n0+2tg+1) d2=(m0+g+8, n0+2tg) d3=(..+1)
    #pragma unroll
    for (int u = 0; u < 10; u++) {
        int nbase = m0 + 8 * u + 2 * tg;
        #pragma unroll
        for (int r = 0; r < 4; r++) {
            int m = m0 + g + 8 * (r >> 1);
            int n = nbase + (r & 1);
            int d = m + 64 - n;
            if (d >= 0 && d < Dn)
                smem[d * TPITCH + m] = dacc[u][r] * 0.03125f;
        }
    }
    __syncthreads();

    // ---- T -> global, coalesced streaming stores ----
    {
        const int dd = tid >> 2;        // d 0..63
        const int wq = tid & 3;
        const float* rowp = smem + dd * TPITCH + 4 * wq;
        float* op = out + ((long)(b * Dn + dd) * Hn + h) * Wn + w0 + 4 * wq;
        #pragma unroll
        for (int k = 0; k < 8; k++) {
            float4 v = *(const float4*)(rowp + 16 * k);
            __stcs((float4*)(op + 16 * k), v);
        }
    }
}

extern "C" void kernel_launch(void* const* d_in, const int* in_sizes, int n_in,
                              void* d_out, int out_size)
{
    const float* left  = (const float*)d_in[0];
    const float* right = (const float*)d_in[1];
    float* out = (float*)d_out;

    dim3 grid(Wn / TW, Hn, Bn);   // (4, 256, 4) = 4096 CTAs
    cost_volume_kernel<<<grid, NT>>>(left, right, out);
}